// round 1
// baseline (speedup 1.0000x reference)
#include <cuda_runtime.h>
#include <math.h>

// FNO block: B=16, C=64, H=W=128, modes 16x16.
// Truncated DFT as small matmuls; everything fp32 on CUDA cores (round 1).

#define NB 16
#define NC 64
#define NH 128
#define NW 128
#define MK 16
#define ML 16
#define NKL 256   // MK*ML

// Scratch (__device__ globals: allocation-free, graph-capture safe)
__device__ float2 g_X [NKL*NB*NC];        // [kl][b][i]   2 MB
__device__ float2 g_Wt[NKL*NC*NC];        // [kl][i][o]   8 MB
__device__ float2 g_OF[NKL*NB*NC];        // [kl][b][o]   2 MB
__device__ float2 g_A [NB*NC*NH*ML];      // [b][o][h][l] 16 MB
__device__ float  g_proj[NB*NC];

// ---------------------------------------------------------------------------
// temb projection: proj[b,o] = sum_c silu(t_emb[b,c]) * temb_w[o,c] + temb_b[o]
// ---------------------------------------------------------------------------
__global__ void k_proj(const float* __restrict__ t_emb,
                       const float* __restrict__ temb_w,
                       const float* __restrict__ temb_b) {
    int bo = blockIdx.x;          // b*64 + o
    int b = bo >> 6, o = bo & 63;
    int tid = threadIdx.x;
    const float* te = t_emb + b * 512;
    const float* tw = temb_w + o * 512;
    float part = 0.f;
    for (int c = tid; c < 512; c += 128) {
        float v = te[c];
        float s = v / (1.f + expf(-v));
        part += s * tw[c];
    }
    for (int off = 16; off; off >>= 1)
        part += __shfl_down_sync(0xffffffffu, part, off);
    __shared__ float ws[4];
    if ((tid & 31) == 0) ws[tid >> 5] = part;
    __syncthreads();
    if (tid == 0) g_proj[bo] = ws[0] + ws[1] + ws[2] + ws[3] + temb_b[o];
}

// ---------------------------------------------------------------------------
// Weight transpose: [i][o][k][l] (2 real planes) -> [kl][i][o] interleaved cplx
// ---------------------------------------------------------------------------
__global__ void k_wt(const float* __restrict__ wr, const float* __restrict__ wi) {
    __shared__ float2 tile[32][33];
    int kl0 = blockIdx.x * 32;   // kl tile
    int io0 = blockIdx.y * 32;   // io tile
    int tx = threadIdx.x, ty = threadIdx.y;
    for (int j = 0; j < 32; j += 8) {
        int io = io0 + ty + j, kl = kl0 + tx;
        tile[ty + j][tx] = make_float2(wr[io * 256 + kl], wi[io * 256 + kl]);
    }
    __syncthreads();
    for (int j = 0; j < 32; j += 8) {
        int kl = kl0 + ty + j, io = io0 + tx;
        g_Wt[kl * 4096 + io] = tile[tx][ty + j];
    }
}

// ---------------------------------------------------------------------------
// Forward truncated DFT per (b,i): X[k,l] = (1/128) * Fh @ x @ Fw^T
// table[n] = e^{-2*pi*i*n/128} = (cos, -sin)
// ---------------------------------------------------------------------------
__global__ void __launch_bounds__(256) k_fwd(const float* __restrict__ x) {
    __shared__ float2 tbl[128];
    __shared__ float  xs[32 * 128];       // 32-row chunk
    __shared__ float2 Ys[128 * 16];       // Y[h][l]
    int tid = threadIdx.x;
    if (tid < 128) {
        float s, c;
        sincospif(tid * (1.0f / 64.0f), &s, &c);
        tbl[tid] = make_float2(c, -s);
    }
    const float* xb = x + (size_t)blockIdx.x * (NH * NW);

    for (int chunk = 0; chunk < 4; chunk++) {
        __syncthreads();
        for (int idx = tid; idx < 4096; idx += 256)
            xs[idx] = xb[chunk * 4096 + idx];
        __syncthreads();
        // stage 1: Y[h][l] = sum_w x[h][w] * e^{-2pi i l w/128}
        #pragma unroll
        for (int p = 0; p < 2; p++) {
            int oi = tid + p * 256;
            int hr = oi >> 4, l = oi & 15;
            const float* row = xs + hr * 128;
            float ar = 0.f, ai = 0.f;
            #pragma unroll 8
            for (int w = 0; w < 128; w++) {
                float2 t = tbl[(l * w) & 127];
                float xv = row[w];
                ar += xv * t.x;
                ai += xv * t.y;
            }
            Ys[(chunk * 32 + hr) * 16 + l] = make_float2(ar, ai);
        }
    }
    __syncthreads();
    // stage 2: X[k][l] = (1/128) sum_h e^{-2pi i k h/128} * Y[h][l]
    int k = tid >> 4, l = tid & 15;
    float ar = 0.f, ai = 0.f;
    #pragma unroll 8
    for (int h = 0; h < 128; h++) {
        float2 t = tbl[(k * h) & 127];
        float2 y = Ys[h * 16 + l];
        ar += t.x * y.x - t.y * y.y;
        ai += t.x * y.y + t.y * y.x;
    }
    g_X[tid * (NB * NC) + blockIdx.x] =
        make_float2(ar * 0.0078125f, ai * 0.0078125f);
}

// ---------------------------------------------------------------------------
// Spectral mix per mode kl: OF[b][o] = sum_i X[b][i] * W[i][o] (complex)
// ---------------------------------------------------------------------------
__global__ void __launch_bounds__(256) k_spec() {
    __shared__ float2 Xs[NB * NC];   // 1024
    __shared__ float2 Ws[NC * NC];   // 4096
    int kl = blockIdx.x, tid = threadIdx.x;
    for (int idx = tid; idx < 1024; idx += 256) Xs[idx] = g_X[kl * 1024 + idx];
    for (int idx = tid; idx < 4096; idx += 256) Ws[idx] = g_Wt[kl * 4096 + idx];
    __syncthreads();
    #pragma unroll
    for (int p = 0; p < 4; p++) {
        int idx = tid + p * 256;
        int b = idx >> 6, o = idx & 63;
        float ar = 0.f, ai = 0.f;
        #pragma unroll 8
        for (int i = 0; i < 64; i++) {
            float2 X = Xs[b * 64 + i];
            float2 W = Ws[i * 64 + o];
            ar += X.x * W.x - X.y * W.y;
            ai += X.x * W.y + X.y * W.x;
        }
        g_OF[kl * 1024 + idx] = make_float2(ar, ai);
    }
}

// ---------------------------------------------------------------------------
// Inverse along h: A[b,o,h,l] = (1/128) sum_k e^{+2pi i k h/128} * F[k,l]
// e^{+i th} = (t.x, -t.y) with table as above.
// ---------------------------------------------------------------------------
__global__ void __launch_bounds__(256) k_invA() {
    __shared__ float2 tbl[128];
    __shared__ float2 Fs[256];
    int tid = threadIdx.x;
    int bo = blockIdx.x;          // b*64 + o
    if (tid < 128) {
        float s, c;
        sincospif(tid * (1.0f / 64.0f), &s, &c);
        tbl[tid] = make_float2(c, -s);
    }
    Fs[tid] = g_OF[tid * 1024 + bo];
    __syncthreads();
    #pragma unroll
    for (int p = 0; p < 8; p++) {
        int idx = tid + p * 256;
        int h = idx >> 4, l = idx & 15;
        float ar = 0.f, ai = 0.f;
        #pragma unroll
        for (int k = 0; k < 16; k++) {
            float2 t = tbl[(k * h) & 127];
            float2 F = Fs[k * 16 + l];
            ar += t.x * F.x + t.y * F.y;   // Re{e^{+i}F}
            ai += t.x * F.y - t.y * F.x;   // Im{e^{+i}F}
        }
        g_A[bo * 2048 + idx] = make_float2(ar * 0.0078125f, ai * 0.0078125f);
    }
}

// ---------------------------------------------------------------------------
// Final fused kernel per (b,h):
//   byp  = bypass_w @ x[:, :, h, :]  (+b)
//   spec = Re(A0) + 2*sum_{l>=1}(ReA cos - ImA sin)
//   out  = gelu(spec + byp) + proj
// ---------------------------------------------------------------------------
__global__ void __launch_bounds__(256) k_final(const float* __restrict__ x,
                                               const float* __restrict__ bypw,
                                               const float* __restrict__ bypb,
                                               float* __restrict__ out) {
    extern __shared__ float sm[];
    float*  xs  = sm;                         // 8192 f
    float*  bw  = xs + 8192;                  // 4096 f
    float2* As  = (float2*)(bw + 4096);       // 1024 f2
    float2* tbl = As + 1024;                  // 128  f2
    float*  pb  = (float*)(tbl + 128);        // 64 f
    float*  pj  = pb + 64;                    // 64 f

    int tid = threadIdx.x;
    int b = blockIdx.x >> 7, h = blockIdx.x & 127;

    if (tid < 128) {
        float s, c;
        sincospif(tid * (1.0f / 64.0f), &s, &c);
        tbl[tid] = make_float2(c, -s);
    }
    const float* xbase = x + (size_t)b * NC * 16384 + h * 128;
    for (int idx = tid; idx < 8192; idx += 256) {
        int i = idx >> 7, w = idx & 127;
        xs[idx] = xbase[i * 16384 + w];
    }
    for (int idx = tid; idx < 4096; idx += 256) bw[idx] = bypw[idx];
    for (int idx = tid; idx < 1024; idx += 256) {
        int o = idx >> 4;
        As[idx] = g_A[(b * 64 + o) * 2048 + h * 16 + (idx & 15)];
    }
    if (tid < 64) { pb[tid] = bypb[tid]; pj[tid] = g_proj[b * 64 + tid]; }
    __syncthreads();

    int wq = tid & 31;     // covers w = 4*wq .. 4*wq+3
    int og = tid >> 5;     // 0..7
    int w0 = wq * 4;
    const float4* xs4 = (const float4*)xs;
    float* obase = out + (size_t)b * NC * 16384 + h * 128;

    #pragma unroll
    for (int pass = 0; pass < 2; pass++) {
        int ob = og * 8 + pass * 4;   // 4 consecutive o channels
        float4 a0 = {0,0,0,0}, a1 = a0, a2 = a0, a3 = a0;
        #pragma unroll 4
        for (int i = 0; i < 64; i++) {
            float4 xv = xs4[i * 32 + wq];
            float b0 = bw[(ob + 0) * 64 + i];
            float b1 = bw[(ob + 1) * 64 + i];
            float b2 = bw[(ob + 2) * 64 + i];
            float b3 = bw[(ob + 3) * 64 + i];
            a0.x += b0 * xv.x; a0.y += b0 * xv.y; a0.z += b0 * xv.z; a0.w += b0 * xv.w;
            a1.x += b1 * xv.x; a1.y += b1 * xv.y; a1.z += b1 * xv.z; a1.w += b1 * xv.w;
            a2.x += b2 * xv.x; a2.y += b2 * xv.y; a2.z += b2 * xv.z; a2.w += b2 * xv.w;
            a3.x += b3 * xv.x; a3.y += b3 * xv.y; a3.z += b3 * xv.z; a3.w += b3 * xv.w;
        }
        // spectral part for 4 o x 4 w
        float dc0 = As[(ob + 0) * 16].x;
        float dc1 = As[(ob + 1) * 16].x;
        float dc2 = As[(ob + 2) * 16].x;
        float dc3 = As[(ob + 3) * 16].x;
        float4 s0 = {dc0,dc0,dc0,dc0}, s1 = {dc1,dc1,dc1,dc1};
        float4 s2 = {dc2,dc2,dc2,dc2}, s3 = {dc3,dc3,dc3,dc3};
        #pragma unroll
        for (int l = 1; l < 16; l++) {
            float2 t0 = tbl[(l * (w0 + 0)) & 127];
            float2 t1 = tbl[(l * (w0 + 1)) & 127];
            float2 t2 = tbl[(l * (w0 + 2)) & 127];
            float2 t3 = tbl[(l * (w0 + 3)) & 127];
            float2 A0 = As[(ob + 0) * 16 + l];
            float2 A1 = As[(ob + 1) * 16 + l];
            float2 A2 = As[(ob + 2) * 16 + l];
            float2 A3 = As[(ob + 3) * 16 + l];
            // ReA*cos - ImA*sin = A.x*t.x + A.y*t.y  (t = (cos,-sin))
            s0.x += 2.f*(A0.x*t0.x + A0.y*t0.y); s0.y += 2.f*(A0.x*t1.x + A0.y*t1.y);
            s0.z += 2.f*(A0.x*t2.x + A0.y*t2.y); s0.w += 2.f*(A0.x*t3.x + A0.y*t3.y);
            s1.x += 2.f*(A1.x*t0.x + A1.y*t0.y); s1.y += 2.f*(A1.x*t1.x + A1.y*t1.y);
            s1.z += 2.f*(A1.x*t2.x + A1.y*t2.y); s1.w += 2.f*(A1.x*t3.x + A1.y*t3.y);
            s2.x += 2.f*(A2.x*t0.x + A2.y*t0.y); s2.y += 2.f*(A2.x*t1.x + A2.y*t1.y);
            s2.z += 2.f*(A2.x*t2.x + A2.y*t2.y); s2.w += 2.f*(A2.x*t3.x + A2.y*t3.y);
            s3.x += 2.f*(A3.x*t0.x + A3.y*t0.y); s3.y += 2.f*(A3.x*t1.x + A3.y*t1.y);
            s3.z += 2.f*(A3.x*t2.x + A3.y*t2.y); s3.w += 2.f*(A3.x*t3.x + A3.y*t3.y);
        }
        float4 acc[4] = {a0, a1, a2, a3};
        float4 spc[4] = {s0, s1, s2, s3};
        #pragma unroll
        for (int j = 0; j < 4; j++) {
            int o = ob + j;
            float bias = pb[o], pr = pj[o];
            float4 v;
            v.x = spc[j].x + acc[j].x + bias;
            v.y = spc[j].y + acc[j].y + bias;
            v.z = spc[j].z + acc[j].z + bias;
            v.w = spc[j].w + acc[j].w + bias;
            const float is2 = 0.70710678118654752f;
            float4 g;
            g.x = 0.5f * v.x * (1.f + erff(v.x * is2)) + pr;
            g.y = 0.5f * v.y * (1.f + erff(v.y * is2)) + pr;
            g.z = 0.5f * v.z * (1.f + erff(v.z * is2)) + pr;
            g.w = 0.5f * v.w * (1.f + erff(v.w * is2)) + pr;
            ((float4*)(obase + o * 16384))[wq] = g;
        }
    }
}

// ---------------------------------------------------------------------------
extern "C" void kernel_launch(void* const* d_in, const int* in_sizes, int n_in,
                              void* d_out, int out_size) {
    const float* x     = (const float*)d_in[0];
    const float* t_emb = (const float*)d_in[1];
    const float* wr    = (const float*)d_in[2];
    const float* wi    = (const float*)d_in[3];
    const float* bypw  = (const float*)d_in[4];
    const float* bypb  = (const float*)d_in[5];
    const float* tw    = (const float*)d_in[6];
    const float* tb    = (const float*)d_in[7];
    float* out = (float*)d_out;

    const int SMEM_FINAL = 8192*4 + 4096*4 + 1024*8 + 128*8 + 64*4 + 64*4; // 58880
    cudaFuncSetAttribute(k_final, cudaFuncAttributeMaxDynamicSharedMemorySize, SMEM_FINAL);

    k_proj<<<NB * NC, 128>>>(t_emb, tw, tb);
    k_wt  <<<dim3(8, 128), dim3(32, 8)>>>(wr, wi);
    k_fwd <<<NB * NC, 256>>>(x);
    k_spec<<<NKL, 256>>>();
    k_invA<<<NB * NC, 256>>>();
    k_final<<<NB * NH, 256, SMEM_FINAL>>>(x, bypw, bypb, out);
}

// round 2
// speedup vs baseline: 1.0006x; 1.0006x over previous
#include <cuda_runtime.h>
#include <math.h>

// FNO block: B=16, C=64, H=W=128, modes 16x16.
// Truncated DFT as small matmuls; everything fp32 on CUDA cores (round 1).

#define NB 16
#define NC 64
#define NH 128
#define NW 128
#define MK 16
#define ML 16
#define NKL 256   // MK*ML

// Scratch (__device__ globals: allocation-free, graph-capture safe)
__device__ float2 g_X [NKL*NB*NC];        // [kl][b][i]   2 MB
__device__ float2 g_Wt[NKL*NC*NC];        // [kl][i][o]   8 MB
__device__ float2 g_OF[NKL*NB*NC];        // [kl][b][o]   2 MB
__device__ float2 g_A [NB*NC*NH*ML];      // [b][o][h][l] 16 MB
__device__ float  g_proj[NB*NC];

// ---------------------------------------------------------------------------
// temb projection: proj[b,o] = sum_c silu(t_emb[b,c]) * temb_w[o,c] + temb_b[o]
// ---------------------------------------------------------------------------
__global__ void k_proj(const float* __restrict__ t_emb,
                       const float* __restrict__ temb_w,
                       const float* __restrict__ temb_b) {
    int bo = blockIdx.x;          // b*64 + o
    int b = bo >> 6, o = bo & 63;
    int tid = threadIdx.x;
    const float* te = t_emb + b * 512;
    const float* tw = temb_w + o * 512;
    float part = 0.f;
    for (int c = tid; c < 512; c += 128) {
        float v = te[c];
        float s = v / (1.f + expf(-v));
        part += s * tw[c];
    }
    for (int off = 16; off; off >>= 1)
        part += __shfl_down_sync(0xffffffffu, part, off);
    __shared__ float ws[4];
    if ((tid & 31) == 0) ws[tid >> 5] = part;
    __syncthreads();
    if (tid == 0) g_proj[bo] = ws[0] + ws[1] + ws[2] + ws[3] + temb_b[o];
}

// ---------------------------------------------------------------------------
// Weight transpose: [i][o][k][l] (2 real planes) -> [kl][i][o] interleaved cplx
// ---------------------------------------------------------------------------
__global__ void k_wt(const float* __restrict__ wr, const float* __restrict__ wi) {
    __shared__ float2 tile[32][33];
    int kl0 = blockIdx.x * 32;   // kl tile
    int io0 = blockIdx.y * 32;   // io tile
    int tx = threadIdx.x, ty = threadIdx.y;
    for (int j = 0; j < 32; j += 8) {
        int io = io0 + ty + j, kl = kl0 + tx;
        tile[ty + j][tx] = make_float2(wr[io * 256 + kl], wi[io * 256 + kl]);
    }
    __syncthreads();
    for (int j = 0; j < 32; j += 8) {
        int kl = kl0 + ty + j, io = io0 + tx;
        g_Wt[kl * 4096 + io] = tile[tx][ty + j];
    }
}

// ---------------------------------------------------------------------------
// Forward truncated DFT per (b,i): X[k,l] = (1/128) * Fh @ x @ Fw^T
// table[n] = e^{-2*pi*i*n/128} = (cos, -sin)
// ---------------------------------------------------------------------------
__global__ void __launch_bounds__(256) k_fwd(const float* __restrict__ x) {
    __shared__ float2 tbl[128];
    __shared__ float  xs[32 * 128];       // 32-row chunk
    __shared__ float2 Ys[128 * 16];       // Y[h][l]
    int tid = threadIdx.x;
    if (tid < 128) {
        float s, c;
        sincospif(tid * (1.0f / 64.0f), &s, &c);
        tbl[tid] = make_float2(c, -s);
    }
    const float* xb = x + (size_t)blockIdx.x * (NH * NW);

    for (int chunk = 0; chunk < 4; chunk++) {
        __syncthreads();
        for (int idx = tid; idx < 4096; idx += 256)
            xs[idx] = xb[chunk * 4096 + idx];
        __syncthreads();
        // stage 1: Y[h][l] = sum_w x[h][w] * e^{-2pi i l w/128}
        #pragma unroll
        for (int p = 0; p < 2; p++) {
            int oi = tid + p * 256;
            int hr = oi >> 4, l = oi & 15;
            const float* row = xs + hr * 128;
            float ar = 0.f, ai = 0.f;
            #pragma unroll 8
            for (int w = 0; w < 128; w++) {
                float2 t = tbl[(l * w) & 127];
                float xv = row[w];
                ar += xv * t.x;
                ai += xv * t.y;
            }
            Ys[(chunk * 32 + hr) * 16 + l] = make_float2(ar, ai);
        }
    }
    __syncthreads();
    // stage 2: X[k][l] = (1/128) sum_h e^{-2pi i k h/128} * Y[h][l]
    int k = tid >> 4, l = tid & 15;
    float ar = 0.f, ai = 0.f;
    #pragma unroll 8
    for (int h = 0; h < 128; h++) {
        float2 t = tbl[(k * h) & 127];
        float2 y = Ys[h * 16 + l];
        ar += t.x * y.x - t.y * y.y;
        ai += t.x * y.y + t.y * y.x;
    }
    g_X[tid * (NB * NC) + blockIdx.x] =
        make_float2(ar * 0.0078125f, ai * 0.0078125f);
}

// ---------------------------------------------------------------------------
// Spectral mix per mode kl: OF[b][o] = sum_i X[b][i] * W[i][o] (complex)
// ---------------------------------------------------------------------------
__global__ void __launch_bounds__(256) k_spec() {
    __shared__ float2 Xs[NB * NC];   // 1024
    __shared__ float2 Ws[NC * NC];   // 4096
    int kl = blockIdx.x, tid = threadIdx.x;
    for (int idx = tid; idx < 1024; idx += 256) Xs[idx] = g_X[kl * 1024 + idx];
    for (int idx = tid; idx < 4096; idx += 256) Ws[idx] = g_Wt[kl * 4096 + idx];
    __syncthreads();
    #pragma unroll
    for (int p = 0; p < 4; p++) {
        int idx = tid + p * 256;
        int b = idx >> 6, o = idx & 63;
        float ar = 0.f, ai = 0.f;
        #pragma unroll 8
        for (int i = 0; i < 64; i++) {
            float2 X = Xs[b * 64 + i];
            float2 W = Ws[i * 64 + o];
            ar += X.x * W.x - X.y * W.y;
            ai += X.x * W.y + X.y * W.x;
        }
        g_OF[kl * 1024 + idx] = make_float2(ar, ai);
    }
}

// ---------------------------------------------------------------------------
// Inverse along h: A[b,o,h,l] = (1/128) sum_k e^{+2pi i k h/128} * F[k,l]
// e^{+i th} = (t.x, -t.y) with table as above.
// ---------------------------------------------------------------------------
__global__ void __launch_bounds__(256) k_invA() {
    __shared__ float2 tbl[128];
    __shared__ float2 Fs[256];
    int tid = threadIdx.x;
    int bo = blockIdx.x;          // b*64 + o
    if (tid < 128) {
        float s, c;
        sincospif(tid * (1.0f / 64.0f), &s, &c);
        tbl[tid] = make_float2(c, -s);
    }
    Fs[tid] = g_OF[tid * 1024 + bo];
    __syncthreads();
    #pragma unroll
    for (int p = 0; p < 8; p++) {
        int idx = tid + p * 256;
        int h = idx >> 4, l = idx & 15;
        float ar = 0.f, ai = 0.f;
        #pragma unroll
        for (int k = 0; k < 16; k++) {
            float2 t = tbl[(k * h) & 127];
            float2 F = Fs[k * 16 + l];
            ar += t.x * F.x + t.y * F.y;   // Re{e^{+i}F}
            ai += t.x * F.y - t.y * F.x;   // Im{e^{+i}F}
        }
        g_A[bo * 2048 + idx] = make_float2(ar * 0.0078125f, ai * 0.0078125f);
    }
}

// ---------------------------------------------------------------------------
// Final fused kernel per (b,h):
//   byp  = bypass_w @ x[:, :, h, :]  (+b)
//   spec = Re(A0) + 2*sum_{l>=1}(ReA cos - ImA sin)
//   out  = gelu(spec + byp) + proj
// ---------------------------------------------------------------------------
__global__ void __launch_bounds__(256) k_final(const float* __restrict__ x,
                                               const float* __restrict__ bypw,
                                               const float* __restrict__ bypb,
                                               float* __restrict__ out) {
    extern __shared__ float sm[];
    float*  xs  = sm;                         // 8192 f
    float*  bw  = xs + 8192;                  // 4096 f
    float2* As  = (float2*)(bw + 4096);       // 1024 f2
    float2* tbl = As + 1024;                  // 128  f2
    float*  pb  = (float*)(tbl + 128);        // 64 f
    float*  pj  = pb + 64;                    // 64 f

    int tid = threadIdx.x;
    int b = blockIdx.x >> 7, h = blockIdx.x & 127;

    if (tid < 128) {
        float s, c;
        sincospif(tid * (1.0f / 64.0f), &s, &c);
        tbl[tid] = make_float2(c, -s);
    }
    const float* xbase = x + (size_t)b * NC * 16384 + h * 128;
    for (int idx = tid; idx < 8192; idx += 256) {
        int i = idx >> 7, w = idx & 127;
        xs[idx] = xbase[i * 16384 + w];
    }
    for (int idx = tid; idx < 4096; idx += 256) bw[idx] = bypw[idx];
    for (int idx = tid; idx < 1024; idx += 256) {
        int o = idx >> 4;
        As[idx] = g_A[(b * 64 + o) * 2048 + h * 16 + (idx & 15)];
    }
    if (tid < 64) { pb[tid] = bypb[tid]; pj[tid] = g_proj[b * 64 + tid]; }
    __syncthreads();

    int wq = tid & 31;     // covers w = 4*wq .. 4*wq+3
    int og = tid >> 5;     // 0..7
    int w0 = wq * 4;
    const float4* xs4 = (const float4*)xs;
    float* obase = out + (size_t)b * NC * 16384 + h * 128;

    #pragma unroll
    for (int pass = 0; pass < 2; pass++) {
        int ob = og * 8 + pass * 4;   // 4 consecutive o channels
        float4 a0 = {0,0,0,0}, a1 = a0, a2 = a0, a3 = a0;
        #pragma unroll 4
        for (int i = 0; i < 64; i++) {
            float4 xv = xs4[i * 32 + wq];
            float b0 = bw[(ob + 0) * 64 + i];
            float b1 = bw[(ob + 1) * 64 + i];
            float b2 = bw[(ob + 2) * 64 + i];
            float b3 = bw[(ob + 3) * 64 + i];
            a0.x += b0 * xv.x; a0.y += b0 * xv.y; a0.z += b0 * xv.z; a0.w += b0 * xv.w;
            a1.x += b1 * xv.x; a1.y += b1 * xv.y; a1.z += b1 * xv.z; a1.w += b1 * xv.w;
            a2.x += b2 * xv.x; a2.y += b2 * xv.y; a2.z += b2 * xv.z; a2.w += b2 * xv.w;
            a3.x += b3 * xv.x; a3.y += b3 * xv.y; a3.z += b3 * xv.z; a3.w += b3 * xv.w;
        }
        // spectral part for 4 o x 4 w
        float dc0 = As[(ob + 0) * 16].x;
        float dc1 = As[(ob + 1) * 16].x;
        float dc2 = As[(ob + 2) * 16].x;
        float dc3 = As[(ob + 3) * 16].x;
        float4 s0 = {dc0,dc0,dc0,dc0}, s1 = {dc1,dc1,dc1,dc1};
        float4 s2 = {dc2,dc2,dc2,dc2}, s3 = {dc3,dc3,dc3,dc3};
        #pragma unroll
        for (int l = 1; l < 16; l++) {
            float2 t0 = tbl[(l * (w0 + 0)) & 127];
            float2 t1 = tbl[(l * (w0 + 1)) & 127];
            float2 t2 = tbl[(l * (w0 + 2)) & 127];
            float2 t3 = tbl[(l * (w0 + 3)) & 127];
            float2 A0 = As[(ob + 0) * 16 + l];
            float2 A1 = As[(ob + 1) * 16 + l];
            float2 A2 = As[(ob + 2) * 16 + l];
            float2 A3 = As[(ob + 3) * 16 + l];
            // ReA*cos - ImA*sin = A.x*t.x + A.y*t.y  (t = (cos,-sin))
            s0.x += 2.f*(A0.x*t0.x + A0.y*t0.y); s0.y += 2.f*(A0.x*t1.x + A0.y*t1.y);
            s0.z += 2.f*(A0.x*t2.x + A0.y*t2.y); s0.w += 2.f*(A0.x*t3.x + A0.y*t3.y);
            s1.x += 2.f*(A1.x*t0.x + A1.y*t0.y); s1.y += 2.f*(A1.x*t1.x + A1.y*t1.y);
            s1.z += 2.f*(A1.x*t2.x + A1.y*t2.y); s1.w += 2.f*(A1.x*t3.x + A1.y*t3.y);
            s2.x += 2.f*(A2.x*t0.x + A2.y*t0.y); s2.y += 2.f*(A2.x*t1.x + A2.y*t1.y);
            s2.z += 2.f*(A2.x*t2.x + A2.y*t2.y); s2.w += 2.f*(A2.x*t3.x + A2.y*t3.y);
            s3.x += 2.f*(A3.x*t0.x + A3.y*t0.y); s3.y += 2.f*(A3.x*t1.x + A3.y*t1.y);
            s3.z += 2.f*(A3.x*t2.x + A3.y*t2.y); s3.w += 2.f*(A3.x*t3.x + A3.y*t3.y);
        }
        float4 acc[4] = {a0, a1, a2, a3};
        float4 spc[4] = {s0, s1, s2, s3};
        #pragma unroll
        for (int j = 0; j < 4; j++) {
            int o = ob + j;
            float bias = pb[o], pr = pj[o];
            float4 v;
            v.x = spc[j].x + acc[j].x + bias;
            v.y = spc[j].y + acc[j].y + bias;
            v.z = spc[j].z + acc[j].z + bias;
            v.w = spc[j].w + acc[j].w + bias;
            const float is2 = 0.70710678118654752f;
            float4 g;
            g.x = 0.5f * v.x * (1.f + erff(v.x * is2)) + pr;
            g.y = 0.5f * v.y * (1.f + erff(v.y * is2)) + pr;
            g.z = 0.5f * v.z * (1.f + erff(v.z * is2)) + pr;
            g.w = 0.5f * v.w * (1.f + erff(v.w * is2)) + pr;
            ((float4*)(obase + o * 16384))[wq] = g;
        }
    }
}

// ---------------------------------------------------------------------------
extern "C" void kernel_launch(void* const* d_in, const int* in_sizes, int n_in,
                              void* d_out, int out_size) {
    const float* x     = (const float*)d_in[0];
    const float* t_emb = (const float*)d_in[1];
    const float* wr    = (const float*)d_in[2];
    const float* wi    = (const float*)d_in[3];
    const float* bypw  = (const float*)d_in[4];
    const float* bypb  = (const float*)d_in[5];
    const float* tw    = (const float*)d_in[6];
    const float* tb    = (const float*)d_in[7];
    float* out = (float*)d_out;

    const int SMEM_FINAL = 8192*4 + 4096*4 + 1024*8 + 128*8 + 64*4 + 64*4; // 58880
    cudaFuncSetAttribute(k_final, cudaFuncAttributeMaxDynamicSharedMemorySize, SMEM_FINAL);

    k_proj<<<NB * NC, 128>>>(t_emb, tw, tb);
    k_wt  <<<dim3(8, 128), dim3(32, 8)>>>(wr, wi);
    k_fwd <<<NB * NC, 256>>>(x);
    k_spec<<<NKL, 256>>>();
    k_invA<<<NB * NC, 256>>>();
    k_final<<<NB * NH, 256, SMEM_FINAL>>>(x, bypw, bypb, out);
}

// round 5
// speedup vs baseline: 1.8208x; 1.8197x over previous
#include <cuda_runtime.h>
#include <math.h>

typedef unsigned long long u64;

__device__ __forceinline__ u64 pk2(float lo, float hi) {
    u64 r; asm("mov.b64 %0, {%1,%2};" : "=l"(r) : "f"(lo), "f"(hi)); return r;
}
__device__ __forceinline__ float2 up2(u64 v) {
    float2 r; asm("mov.b64 {%0,%1}, %2;" : "=f"(r.x), "=f"(r.y) : "l"(v)); return r;
}
__device__ __forceinline__ void fma2(u64& d, u64 a, u64 b) {
    asm("fma.rn.f32x2 %0, %1, %2, %3;" : "=l"(d) : "l"(a), "l"(b), "l"(d));
}
__device__ __forceinline__ float hadd(u64 v) { float2 t = up2(v); return t.x + t.y; }

__device__ float g_Xx [256*1024];
__device__ float g_Xy [256*1024];
__device__ float g_Wtx[256*4096];
__device__ float g_Wty[256*4096];
__device__ float g_OFx[1024*256];
__device__ float g_OFy[1024*256];
__device__ float g_Ax [16*128*64*16];   // [b][h][o][l], scaled, 2x folded
__device__ float g_Ay [16*128*64*16];
__device__ u64   g_bw2[4096];           // [i][o] dup-packed
__device__ float g_proj[1024];

__global__ void k_proj(const float* __restrict__ t_emb, const float* __restrict__ temb_w,
                       const float* __restrict__ temb_b) {
    int bo = blockIdx.x, b = bo >> 6, o = bo & 63, tid = threadIdx.x;
    const float* te = t_emb + b * 512;
    const float* tw = temb_w + o * 512;
    float part = 0.f;
    for (int c = tid; c < 512; c += 128) {
        float v = te[c];
        part += (v / (1.f + expf(-v))) * tw[c];
    }
    for (int off = 16; off; off >>= 1) part += __shfl_down_sync(~0u, part, off);
    __shared__ float ws[4];
    if ((tid & 31) == 0) ws[tid >> 5] = part;
    __syncthreads();
    if (tid == 0) g_proj[bo] = ws[0] + ws[1] + ws[2] + ws[3] + temb_b[o];
}

// weights [i][o][kl] -> SoA [kl][o*64+i]
__global__ void k_wt(const float* __restrict__ wr, const float* __restrict__ wi) {
    __shared__ float tr[32][33], ti[32][33];
    int kl0 = blockIdx.x * 32, io0 = blockIdx.y * 32;
    int tx = threadIdx.x, ty = threadIdx.y;
    #pragma unroll
    for (int j = 0; j < 32; j += 8) {
        int io = io0 + ty + j;
        tr[ty + j][tx] = wr[io * 256 + kl0 + tx];
        ti[ty + j][tx] = wi[io * 256 + kl0 + tx];
    }
    __syncthreads();
    #pragma unroll
    for (int j = 0; j < 32; j += 8) {
        int kl = kl0 + ty + j, io = io0 + tx;
        int i = io >> 6, o = io & 63;
        g_Wtx[kl * 4096 + o * 64 + i] = tr[tx][ty + j];
        g_Wty[kl * 4096 + o * 64 + i] = ti[tx][ty + j];
    }
}

__global__ void k_bwt(const float* __restrict__ bypw) {
    int t = blockIdx.x * 256 + threadIdx.x;
    int i = t >> 6, o = t & 63;
    float v = bypw[o * 64 + i];
    g_bw2[i * 64 + o] = pk2(v, v);
}

// forward truncated DFT per (b,i)
__global__ void __launch_bounds__(256, 2) k_fwd(const float* __restrict__ x) {
    extern __shared__ char sm[];
    float* xs  = (float*)sm;                // 128 x 132
    u64*   tc  = (u64*)(sm + 67584);        // 16 x 65 pair table (cos)
    u64*   ts  = (u64*)(sm + 75904);        // (-sin)
    float* Ysx = (float*)(sm + 84224);      // [l][h] stride 130
    float* Ysy = (float*)(sm + 92544);
    int tid = threadIdx.x;
    const float* xb = x + (size_t)blockIdx.x * 16384;

    #pragma unroll
    for (int j = 0; j < 16; j++) {
        int idx4 = tid + j * 256;
        int row = idx4 >> 5, wq = idx4 & 31;
        *(float4*)(xs + row * 132 + wq * 4) = ((const float4*)xb)[idx4];
    }
    for (int e = tid; e < 1024; e += 256) {
        int m = e >> 6, p = e & 63;
        float s0, c0, s1, c1;
        sincospif((float)(m * (2 * p))     * (1.f / 64.f), &s0, &c0);
        sincospif((float)(m * (2 * p + 1)) * (1.f / 64.f), &s1, &c1);
        tc[m * 65 + p] = pk2(c0, c1);
        ts[m * 65 + p] = pk2(-s0, -s1);
    }
    __syncthreads();

    { // stage 1: Y[l][h] = sum_w x[h][w] e^{-i l w th}
        int h0 = (tid >> 3) * 4, l0 = (tid & 7) * 2;
        u64 aR[4][2], aI[4][2];
        #pragma unroll
        for (int r = 0; r < 4; r++) { aR[r][0]=aR[r][1]=aI[r][0]=aI[r][1]=0ull; }
        #pragma unroll 2
        for (int w = 0; w < 128; w += 4) {
            int wp = w >> 1;
            ulonglong2 x0 = *(ulonglong2*)(xs + (h0+0)*132 + w);
            ulonglong2 x1 = *(ulonglong2*)(xs + (h0+1)*132 + w);
            ulonglong2 x2 = *(ulonglong2*)(xs + (h0+2)*132 + w);
            ulonglong2 x3 = *(ulonglong2*)(xs + (h0+3)*132 + w);
            #pragma unroll
            for (int c = 0; c < 2; c++) {
                int l = l0 + c;
                u64 c0 = tc[l*65+wp], c1 = tc[l*65+wp+1];
                u64 s0 = ts[l*65+wp], s1 = ts[l*65+wp+1];
                fma2(aR[0][c], x0.x, c0); fma2(aR[0][c], x0.y, c1);
                fma2(aI[0][c], x0.x, s0); fma2(aI[0][c], x0.y, s1);
                fma2(aR[1][c], x1.x, c0); fma2(aR[1][c], x1.y, c1);
                fma2(aI[1][c], x1.x, s0); fma2(aI[1][c], x1.y, s1);
                fma2(aR[2][c], x2.x, c0); fma2(aR[2][c], x2.y, c1);
                fma2(aI[2][c], x2.x, s0); fma2(aI[2][c], x2.y, s1);
                fma2(aR[3][c], x3.x, c0); fma2(aR[3][c], x3.y, c1);
                fma2(aI[3][c], x3.x, s0); fma2(aI[3][c], x3.y, s1);
            }
        }
        #pragma unroll
        for (int r = 0; r < 4; r++)
            #pragma unroll
            for (int c = 0; c < 2; c++) {
                Ysx[(l0+c)*130 + h0+r] = hadd(aR[r][c]);
                Ysy[(l0+c)*130 + h0+r] = hadd(aI[r][c]);
            }
    }
    __syncthreads();

    { // stage 2: X[k][l] = (1/128) sum_h e^{-i k h th} Y[h][l]
        int k = tid >> 4, l = tid & 15;
        u64 aA=0ull, aB=0ull, aC=0ull, aD=0ull;
        #pragma unroll 8
        for (int hp = 0; hp < 64; hp++) {
            u64 tck = tc[k*65+hp], tsk = ts[k*65+hp];
            u64 Yxp = *(u64*)(Ysx + l*130 + 2*hp);
            u64 Yyp = *(u64*)(Ysy + l*130 + 2*hp);
            fma2(aA, tck, Yxp); fma2(aB, tsk, Yyp);
            fma2(aC, tck, Yyp); fma2(aD, tsk, Yxp);
        }
        g_Xx[tid*1024 + blockIdx.x] = (hadd(aA) - hadd(aB)) * 0.0078125f;
        g_Xy[tid*1024 + blockIdx.x] = (hadd(aC) + hadd(aD)) * 0.0078125f;
    }
}

// spectral mix per mode kl
__global__ void __launch_bounds__(256) k_spec() {
    __shared__ float Xxs[1024], Xys[1024];
    __shared__ float Wxs[64*66], Wys[64*66];
    int kl = blockIdx.x, tid = threadIdx.x;
    for (int j = tid; j < 1024; j += 256) { Xxs[j] = g_Xx[kl*1024+j]; Xys[j] = g_Xy[kl*1024+j]; }
    for (int j = tid; j < 4096; j += 256) {
        int o = j >> 6, i = j & 63;
        Wxs[o*66+i] = g_Wtx[kl*4096+j];
        Wys[o*66+i] = g_Wty[kl*4096+j];
    }
    __syncthreads();
    int b = tid >> 4, o0 = tid & 15;
    u64 aA[4], aB[4], aC[4], aD[4];
    #pragma unroll
    for (int j = 0; j < 4; j++) { aA[j]=aB[j]=aC[j]=aD[j]=0ull; }
    #pragma unroll 4
    for (int ip = 0; ip < 32; ip++) {
        u64 Xxp = *(u64*)(Xxs + b*64 + 2*ip);
        u64 Xyp = *(u64*)(Xys + b*64 + 2*ip);
        #pragma unroll
        for (int j = 0; j < 4; j++) {
            int o = o0 + 16*j;
            u64 Wxp = *(u64*)(Wxs + o*66 + 2*ip);
            u64 Wyp = *(u64*)(Wys + o*66 + 2*ip);
            fma2(aA[j], Xxp, Wxp); fma2(aB[j], Xyp, Wyp);
            fma2(aC[j], Xxp, Wyp); fma2(aD[j], Xyp, Wxp);
        }
    }
    #pragma unroll
    for (int j = 0; j < 4; j++) {
        int bo = b*64 + o0 + 16*j;
        g_OFx[bo*256 + kl] = hadd(aA[j]) - hadd(aB[j]);
        g_OFy[bo*256 + kl] = hadd(aC[j]) + hadd(aD[j]);
    }
}

// inverse along h per (b,o): A[h][l] = sc * sum_k F[k,l] e^{+i k h th}
__global__ void __launch_bounds__(256) k_invA() {
    __shared__ u64 tcT[128*9], tsT[128*9];
    __shared__ float Fxs[16*18], Fys[16*18];
    int tid = threadIdx.x, bo = blockIdx.x;
    for (int e = tid; e < 1024; e += 256) {
        int h = e >> 3, kp = e & 7;
        float s0, c0, s1, c1;
        sincospif((float)(h * (2*kp))   * (1.f/64.f), &s0, &c0);
        sincospif((float)(h * (2*kp+1)) * (1.f/64.f), &s1, &c1);
        tcT[h*9+kp] = pk2(c0, c1);
        tsT[h*9+kp] = pk2(-s0, -s1);
    }
    {
        int k = tid >> 4, l = tid & 15;
        Fxs[l*18+k] = g_OFx[bo*256 + tid];
        Fys[l*18+k] = g_OFy[bo*256 + tid];
    }
    __syncthreads();
    int h = tid >> 1, l0 = (tid & 1) * 8;
    u64 aA[8], aB[8], aC[8], aD[8];
    #pragma unroll
    for (int j = 0; j < 8; j++) { aA[j]=aB[j]=aC[j]=aD[j]=0ull; }
    #pragma unroll
    for (int kp = 0; kp < 8; kp++) {
        u64 tck = tcT[h*9+kp], tsk = tsT[h*9+kp];
        #pragma unroll
        for (int j = 0; j < 8; j++) {
            u64 Fxp = *(u64*)(Fxs + (l0+j)*18 + 2*kp);
            u64 Fyp = *(u64*)(Fys + (l0+j)*18 + 2*kp);
            fma2(aA[j], tck, Fxp); fma2(aB[j], tsk, Fyp);
            fma2(aC[j], tck, Fyp); fma2(aD[j], tsk, Fxp);
        }
    }
    int b = bo >> 6, o = bo & 63;
    float* ox = g_Ax + ((size_t)(b*128 + h)*64 + o)*16 + l0;
    float* oy = g_Ay + ((size_t)(b*128 + h)*64 + o)*16 + l0;
    float rx[8], ry[8];
    #pragma unroll
    for (int j = 0; j < 8; j++) {
        float sc = (l0 + j == 0) ? 0.0078125f : 0.015625f;
        rx[j] = (hadd(aA[j]) + hadd(aB[j])) * sc;  // Re{e^{+i}F}
        ry[j] = (hadd(aC[j]) - hadd(aD[j])) * sc;  // Im{e^{+i}F}
    }
    *(float4*)(ox)   = make_float4(rx[0],rx[1],rx[2],rx[3]);
    *(float4*)(ox+4) = make_float4(rx[4],rx[5],rx[6],rx[7]);
    *(float4*)(oy)   = make_float4(ry[0],ry[1],ry[2],ry[3]);
    *(float4*)(oy+4) = make_float4(ry[4],ry[5],ry[6],ry[7]);
}

// final fused per (b,h): bypass GEMM + irfft-w + GeLU + temb
__global__ void __launch_bounds__(256, 2) k_final(const float* __restrict__ x,
                                                  const float* __restrict__ bypb,
                                                  float* __restrict__ out) {
    extern __shared__ char sm[];
    float* xs  = (float*)sm;            // 64 x 132
    u64*   bwd = (u64*)(sm + 33792);    // [i][o]
    u64*   Ax2 = (u64*)(sm + 66560);    // [o*16+l] dup
    u64*   Ay2 = (u64*)(sm + 74752);
    u64*   tcw = (u64*)(sm + 82944);    // [l][wp] 16 x 66
    u64*   tsw = (u64*)(sm + 91392);
    float* pb  = (float*)(sm + 99840);
    float* pj  = (float*)(sm + 100096);

    int tid = threadIdx.x;
    int b = blockIdx.x >> 7, h = blockIdx.x & 127;
    const float* xbase = x + (size_t)b * 64 * 16384 + h * 128;

    #pragma unroll
    for (int j = 0; j < 8; j++) {
        int idx4 = tid + j * 256;
        int i = idx4 >> 5, wq = idx4 & 31;
        *(float4*)(xs + i*132 + wq*4) = *(const float4*)(xbase + i*16384 + wq*4);
    }
    #pragma unroll
    for (int j = 0; j < 8; j++)
        ((ulonglong2*)bwd)[tid + j*256] = ((const ulonglong2*)g_bw2)[tid + j*256];
    {
        const float* Abx = g_Ax + (size_t)(b*128 + h) * 1024;
        const float* Aby = g_Ay + (size_t)(b*128 + h) * 1024;
        float4 vx = *(const float4*)(Abx + tid*4);
        float4 vy = *(const float4*)(Aby + tid*4);
        Ax2[tid*4+0] = pk2(vx.x,vx.x); Ax2[tid*4+1] = pk2(vx.y,vx.y);
        Ax2[tid*4+2] = pk2(vx.z,vx.z); Ax2[tid*4+3] = pk2(vx.w,vx.w);
        Ay2[tid*4+0] = pk2(vy.x,vy.x); Ay2[tid*4+1] = pk2(vy.y,vy.y);
        Ay2[tid*4+2] = pk2(vy.z,vy.z); Ay2[tid*4+3] = pk2(vy.w,vy.w);
    }
    for (int e = tid; e < 1024; e += 256) {
        int l = e >> 6, wp = e & 63;
        float s0, c0, s1, c1;
        sincospif((float)(l * (2*wp))   * (1.f/64.f), &s0, &c0);
        sincospif((float)(l * (2*wp+1)) * (1.f/64.f), &s1, &c1);
        tcw[l*66+wp] = pk2(c0, c1);
        tsw[l*66+wp] = pk2(-s0, -s1);
    }
    if (tid < 64) { pb[tid] = bypb[tid]; pj[tid] = g_proj[b*64 + tid]; }
    __syncthreads();

    int o0 = (tid >> 4) * 4, wg = tid & 15, w0 = wg * 8;
    u64 acc[4][4];
    #pragma unroll
    for (int j = 0; j < 4; j++) { acc[j][0]=acc[j][1]=acc[j][2]=acc[j][3]=0ull; }

    #pragma unroll 4
    for (int i = 0; i < 64; i++) {
        ulonglong2 xa = *(ulonglong2*)(xs + i*132 + w0);
        ulonglong2 xc = *(ulonglong2*)(xs + i*132 + w0 + 4);
        ulonglong2 b01 = *(ulonglong2*)(bwd + i*64 + o0);
        ulonglong2 b23 = *(ulonglong2*)(bwd + i*64 + o0 + 2);
        fma2(acc[0][0], b01.x, xa.x); fma2(acc[0][1], b01.x, xa.y);
        fma2(acc[0][2], b01.x, xc.x); fma2(acc[0][3], b01.x, xc.y);
        fma2(acc[1][0], b01.y, xa.x); fma2(acc[1][1], b01.y, xa.y);
        fma2(acc[1][2], b01.y, xc.x); fma2(acc[1][3], b01.y, xc.y);
        fma2(acc[2][0], b23.x, xa.x); fma2(acc[2][1], b23.x, xa.y);
        fma2(acc[2][2], b23.x, xc.x); fma2(acc[2][3], b23.x, xc.y);
        fma2(acc[3][0], b23.y, xa.x); fma2(acc[3][1], b23.y, xa.y);
        fma2(acc[3][2], b23.y, xc.x); fma2(acc[3][3], b23.y, xc.y);
    }
    #pragma unroll 4
    for (int l = 0; l < 16; l++) {
        ulonglong2 c0 = *(ulonglong2*)(tcw + l*66 + wg*4);
        ulonglong2 c1 = *(ulonglong2*)(tcw + l*66 + wg*4 + 2);
        ulonglong2 s0 = *(ulonglong2*)(tsw + l*66 + wg*4);
        ulonglong2 s1 = *(ulonglong2*)(tsw + l*66 + wg*4 + 2);
        #pragma unroll
        for (int j = 0; j < 4; j++) {
            u64 ax = Ax2[(o0+j)*16 + l];
            u64 ay = Ay2[(o0+j)*16 + l];
            fma2(acc[j][0], ax, c0.x); fma2(acc[j][0], ay, s0.x);
            fma2(acc[j][1], ax, c0.y); fma2(acc[j][1], ay, s0.y);
            fma2(acc[j][2], ax, c1.x); fma2(acc[j][2], ay, s1.x);
            fma2(acc[j][3], ax, c1.y); fma2(acc[j][3], ay, s1.y);
        }
    }
    float* obase = out + (size_t)b * 64 * 16384 + h * 128 + w0;
    const float is2 = 0.70710678118654752f;
    #pragma unroll
    for (int j = 0; j < 4; j++) {
        int o = o0 + j;
        float bias = pb[o], pr = pj[o];
        float g[8];
        #pragma unroll
        for (int p = 0; p < 4; p++) {
            float2 t = up2(acc[j][p]);
            float v0 = t.x + bias, v1 = t.y + bias;
            g[2*p]   = 0.5f * v0 * (1.f + erff(v0 * is2)) + pr;
            g[2*p+1] = 0.5f * v1 * (1.f + erff(v1 * is2)) + pr;
        }
        *(float4*)(obase + o*16384)     = make_float4(g[0],g[1],g[2],g[3]);
        *(float4*)(obase + o*16384 + 4) = make_float4(g[4],g[5],g[6],g[7]);
    }
}

extern "C" void kernel_launch(void* const* d_in, const int* in_sizes, int n_in,
                              void* d_out, int out_size) {
    const float* x     = (const float*)d_in[0];
    const float* t_emb = (const float*)d_in[1];
    const float* wr    = (const float*)d_in[2];
    const float* wi    = (const float*)d_in[3];
    const float* bypw  = (const float*)d_in[4];
    const float* bypb  = (const float*)d_in[5];
    const float* tw    = (const float*)d_in[6];
    const float* tb    = (const float*)d_in[7];
    float* out = (float*)d_out;

    cudaFuncSetAttribute(k_fwd,   cudaFuncAttributeMaxDynamicSharedMemorySize, 100864);
    cudaFuncSetAttribute(k_final, cudaFuncAttributeMaxDynamicSharedMemorySize, 100352);

    k_proj<<<1024, 128>>>(t_emb, tw, tb);
    k_wt  <<<dim3(8, 128), dim3(32, 8)>>>(wr, wi);
    k_bwt <<<16, 256>>>(bypw);
    k_fwd <<<1024, 256, 100864>>>(x);
    k_spec<<<256, 256>>>();
    k_invA<<<1024, 256>>>();
    k_final<<<2048, 256, 100352>>>(x, bypb, out);
}

// round 6
// speedup vs baseline: 2.0698x; 1.1368x over previous
#include <cuda_runtime.h>
#include <math.h>

typedef unsigned long long u64;

__device__ __forceinline__ u64 pk2(float lo, float hi) {
    u64 r; asm("mov.b64 %0, {%1,%2};" : "=l"(r) : "f"(lo), "f"(hi)); return r;
}
__device__ __forceinline__ float2 up2(u64 v) {
    float2 r; asm("mov.b64 {%0,%1}, %2;" : "=f"(r.x), "=f"(r.y) : "l"(v)); return r;
}
__device__ __forceinline__ void fma2(u64& d, u64 a, u64 b) {
    asm("fma.rn.f32x2 %0, %1, %2, %3;" : "=l"(d) : "l"(a), "l"(b), "l"(d));
}
__device__ __forceinline__ float hadd(u64 v) { float2 t = up2(v); return t.x + t.y; }

__device__ float g_Xx [256*1024];
__device__ float g_Xy [256*1024];
__device__ float g_Wtx[256*4096];
__device__ float g_Wty[256*4096];
__device__ float g_OFx[1024*256];
__device__ float g_OFy[1024*256];
__device__ float g_Ax [16*128*64*16];   // [b][h][o][l], scaled, 2x folded
__device__ float g_Ay [16*128*64*16];
__device__ u64   g_bw2[4096];           // [i][o] dup-packed
__device__ float g_proj[1024];

__global__ void k_proj(const float* __restrict__ t_emb, const float* __restrict__ temb_w,
                       const float* __restrict__ temb_b) {
    int bo = blockIdx.x, b = bo >> 6, o = bo & 63, tid = threadIdx.x;
    const float* te = t_emb + b * 512;
    const float* tw = temb_w + o * 512;
    float part = 0.f;
    for (int c = tid; c < 512; c += 128) {
        float v = te[c];
        part += (v / (1.f + expf(-v))) * tw[c];
    }
    for (int off = 16; off; off >>= 1) part += __shfl_down_sync(~0u, part, off);
    __shared__ float ws[4];
    if ((tid & 31) == 0) ws[tid >> 5] = part;
    __syncthreads();
    if (tid == 0) g_proj[bo] = ws[0] + ws[1] + ws[2] + ws[3] + temb_b[o];
}

// weights [i][o][kl] -> SoA [kl][o*64+i]
__global__ void k_wt(const float* __restrict__ wr, const float* __restrict__ wi) {
    __shared__ float tr[32][33], ti[32][33];
    int kl0 = blockIdx.x * 32, io0 = blockIdx.y * 32;
    int tx = threadIdx.x, ty = threadIdx.y;
    #pragma unroll
    for (int j = 0; j < 32; j += 8) {
        int io = io0 + ty + j;
        tr[ty + j][tx] = wr[io * 256 + kl0 + tx];
        ti[ty + j][tx] = wi[io * 256 + kl0 + tx];
    }
    __syncthreads();
    #pragma unroll
    for (int j = 0; j < 32; j += 8) {
        int kl = kl0 + ty + j, io = io0 + tx;
        int i = io >> 6, o = io & 63;
        g_Wtx[kl * 4096 + o * 64 + i] = tr[tx][ty + j];
        g_Wty[kl * 4096 + o * 64 + i] = ti[tx][ty + j];
    }
}

__global__ void k_bwt(const float* __restrict__ bypw) {
    int t = blockIdx.x * 256 + threadIdx.x;
    int i = t >> 6, o = t & 63;
    float v = bypw[o * 64 + i];
    g_bw2[i * 64 + o] = pk2(v, v);
}

// forward truncated DFT per (b,i)
__global__ void __launch_bounds__(256, 2) k_fwd(const float* __restrict__ x) {
    extern __shared__ char sm[];
    float* xs  = (float*)sm;                // 128 x 132
    u64*   tc  = (u64*)(sm + 67584);        // 16 x 65 pair table (cos)
    u64*   ts  = (u64*)(sm + 75904);        // (-sin)
    float* Ysx = (float*)(sm + 84224);      // [l][h] stride 130
    float* Ysy = (float*)(sm + 92544);
    int tid = threadIdx.x;
    const float* xb = x + (size_t)blockIdx.x * 16384;

    #pragma unroll
    for (int j = 0; j < 16; j++) {
        int idx4 = tid + j * 256;
        int row = idx4 >> 5, wq = idx4 & 31;
        *(float4*)(xs + row * 132 + wq * 4) = ((const float4*)xb)[idx4];
    }
    for (int e = tid; e < 1024; e += 256) {
        int m = e >> 6, p = e & 63;
        float s0, c0, s1, c1;
        sincospif((float)(m * (2 * p))     * (1.f / 64.f), &s0, &c0);
        sincospif((float)(m * (2 * p + 1)) * (1.f / 64.f), &s1, &c1);
        tc[m * 65 + p] = pk2(c0, c1);
        ts[m * 65 + p] = pk2(-s0, -s1);
    }
    __syncthreads();

    { // stage 1: Y[l][h] = sum_w x[h][w] e^{-i l w th}
      // rows interleaved: h = h_low + 32*r  (conflict-free x loads)
        int h_low = tid >> 3, l0 = (tid & 7) * 2;
        u64 aR[4][2], aI[4][2];
        #pragma unroll
        for (int r = 0; r < 4; r++) { aR[r][0]=aR[r][1]=aI[r][0]=aI[r][1]=0ull; }
        #pragma unroll 2
        for (int w = 0; w < 128; w += 4) {
            int wp = w >> 1;
            ulonglong2 x0 = *(ulonglong2*)(xs + (h_low +  0)*132 + w);
            ulonglong2 x1 = *(ulonglong2*)(xs + (h_low + 32)*132 + w);
            ulonglong2 x2 = *(ulonglong2*)(xs + (h_low + 64)*132 + w);
            ulonglong2 x3 = *(ulonglong2*)(xs + (h_low + 96)*132 + w);
            #pragma unroll
            for (int c = 0; c < 2; c++) {
                int l = l0 + c;
                u64 c0 = tc[l*65+wp], c1 = tc[l*65+wp+1];
                u64 s0 = ts[l*65+wp], s1 = ts[l*65+wp+1];
                fma2(aR[0][c], x0.x, c0); fma2(aR[0][c], x0.y, c1);
                fma2(aI[0][c], x0.x, s0); fma2(aI[0][c], x0.y, s1);
                fma2(aR[1][c], x1.x, c0); fma2(aR[1][c], x1.y, c1);
                fma2(aI[1][c], x1.x, s0); fma2(aI[1][c], x1.y, s1);
                fma2(aR[2][c], x2.x, c0); fma2(aR[2][c], x2.y, c1);
                fma2(aI[2][c], x2.x, s0); fma2(aI[2][c], x2.y, s1);
                fma2(aR[3][c], x3.x, c0); fma2(aR[3][c], x3.y, c1);
                fma2(aI[3][c], x3.x, s0); fma2(aI[3][c], x3.y, s1);
            }
        }
        #pragma unroll
        for (int r = 0; r < 4; r++)
            #pragma unroll
            for (int c = 0; c < 2; c++) {
                Ysx[(l0+c)*130 + h_low + 32*r] = hadd(aR[r][c]);
                Ysy[(l0+c)*130 + h_low + 32*r] = hadd(aI[r][c]);
            }
    }
    __syncthreads();

    { // stage 2: X[k][l] = (1/128) sum_h e^{-i k h th} Y[h][l]
        int k = tid >> 4, l = tid & 15;
        u64 aA=0ull, aB=0ull, aC=0ull, aD=0ull;
        #pragma unroll 8
        for (int hp = 0; hp < 64; hp++) {
            u64 tck = tc[k*65+hp], tsk = ts[k*65+hp];
            u64 Yxp = *(u64*)(Ysx + l*130 + 2*hp);
            u64 Yyp = *(u64*)(Ysy + l*130 + 2*hp);
            fma2(aA, tck, Yxp); fma2(aB, tsk, Yyp);
            fma2(aC, tck, Yyp); fma2(aD, tsk, Yxp);
        }
        g_Xx[tid*1024 + blockIdx.x] = (hadd(aA) - hadd(aB)) * 0.0078125f;
        g_Xy[tid*1024 + blockIdx.x] = (hadd(aC) + hadd(aD)) * 0.0078125f;
    }
}

// spectral mix per mode kl
__global__ void __launch_bounds__(256) k_spec() {
    __shared__ float Xxs[1024], Xys[1024];
    __shared__ float Wxs[64*66], Wys[64*66];
    int kl = blockIdx.x, tid = threadIdx.x;
    for (int j = tid; j < 1024; j += 256) { Xxs[j] = g_Xx[kl*1024+j]; Xys[j] = g_Xy[kl*1024+j]; }
    for (int j = tid; j < 4096; j += 256) {
        int o = j >> 6, i = j & 63;
        Wxs[o*66+i] = g_Wtx[kl*4096+j];
        Wys[o*66+i] = g_Wty[kl*4096+j];
    }
    __syncthreads();
    int b = tid >> 4, o0 = tid & 15;
    u64 aA[4], aB[4], aC[4], aD[4];
    #pragma unroll
    for (int j = 0; j < 4; j++) { aA[j]=aB[j]=aC[j]=aD[j]=0ull; }
    #pragma unroll 4
    for (int ip = 0; ip < 32; ip++) {
        u64 Xxp = *(u64*)(Xxs + b*64 + 2*ip);
        u64 Xyp = *(u64*)(Xys + b*64 + 2*ip);
        #pragma unroll
        for (int j = 0; j < 4; j++) {
            int o = o0 + 16*j;
            u64 Wxp = *(u64*)(Wxs + o*66 + 2*ip);
            u64 Wyp = *(u64*)(Wys + o*66 + 2*ip);
            fma2(aA[j], Xxp, Wxp); fma2(aB[j], Xyp, Wyp);
            fma2(aC[j], Xxp, Wyp); fma2(aD[j], Xyp, Wxp);
        }
    }
    #pragma unroll
    for (int j = 0; j < 4; j++) {
        int bo = b*64 + o0 + 16*j;
        g_OFx[bo*256 + kl] = hadd(aA[j]) - hadd(aB[j]);
        g_OFy[bo*256 + kl] = hadd(aC[j]) + hadd(aD[j]);
    }
}

// inverse along h per (b,o): A[h][l] = sc * sum_k F[k,l] e^{+i k h th}
__global__ void __launch_bounds__(256) k_invA() {
    __shared__ u64 tcT[128*9], tsT[128*9];
    __shared__ float Fxs[16*18], Fys[16*18];
    int tid = threadIdx.x, bo = blockIdx.x;
    for (int e = tid; e < 1024; e += 256) {
        int h = e >> 3, kp = e & 7;
        float s0, c0, s1, c1;
        sincospif((float)(h * (2*kp))   * (1.f/64.f), &s0, &c0);
        sincospif((float)(h * (2*kp+1)) * (1.f/64.f), &s1, &c1);
        tcT[h*9+kp] = pk2(c0, c1);
        tsT[h*9+kp] = pk2(-s0, -s1);
    }
    {
        int k = tid >> 4, l = tid & 15;
        Fxs[l*18+k] = g_OFx[bo*256 + tid];
        Fys[l*18+k] = g_OFy[bo*256 + tid];
    }
    __syncthreads();
    int h = tid >> 1, l0 = (tid & 1) * 8;
    u64 aA[8], aB[8], aC[8], aD[8];
    #pragma unroll
    for (int j = 0; j < 8; j++) { aA[j]=aB[j]=aC[j]=aD[j]=0ull; }
    #pragma unroll
    for (int kp = 0; kp < 8; kp++) {
        u64 tck = tcT[h*9+kp], tsk = tsT[h*9+kp];
        #pragma unroll
        for (int j = 0; j < 8; j++) {
            u64 Fxp = *(u64*)(Fxs + (l0+j)*18 + 2*kp);
            u64 Fyp = *(u64*)(Fys + (l0+j)*18 + 2*kp);
            fma2(aA[j], tck, Fxp); fma2(aB[j], tsk, Fyp);
            fma2(aC[j], tck, Fyp); fma2(aD[j], tsk, Fxp);
        }
    }
    int b = bo >> 6, o = bo & 63;
    float* ox = g_Ax + ((size_t)(b*128 + h)*64 + o)*16 + l0;
    float* oy = g_Ay + ((size_t)(b*128 + h)*64 + o)*16 + l0;
    float rx[8], ry[8];
    #pragma unroll
    for (int j = 0; j < 8; j++) {
        float sc = (l0 + j == 0) ? 0.0078125f : 0.015625f;
        rx[j] = (hadd(aA[j]) + hadd(aB[j])) * sc;  // Re{e^{+i}F}
        ry[j] = (hadd(aC[j]) - hadd(aD[j])) * sc;  // Im{e^{+i}F}
    }
    *(float4*)(ox)   = make_float4(rx[0],rx[1],rx[2],rx[3]);
    *(float4*)(ox+4) = make_float4(rx[4],rx[5],rx[6],rx[7]);
    *(float4*)(oy)   = make_float4(ry[0],ry[1],ry[2],ry[3]);
    *(float4*)(oy+4) = make_float4(ry[4],ry[5],ry[6],ry[7]);
}

// final fused per (b,h): bypass GEMM + irfft-w + GeLU + temb
// thread covers w in {4L..4L+3} and {64+4L..64+4L+3}  (2-way minimal LDS phases)
__global__ void __launch_bounds__(256, 2) k_final(const float* __restrict__ x,
                                                  const float* __restrict__ bypb,
                                                  float* __restrict__ out) {
    extern __shared__ char sm[];
    float* xs  = (float*)sm;            // 64 x 132
    u64*   bwd = (u64*)(sm + 33792);    // [i][o]
    u64*   Ax2 = (u64*)(sm + 66560);    // [o*16+l] dup
    u64*   Ay2 = (u64*)(sm + 74752);
    u64*   tcw = (u64*)(sm + 82944);    // [l][wp] 16 x 66
    u64*   tsw = (u64*)(sm + 91392);
    float* pb  = (float*)(sm + 99840);
    float* pj  = (float*)(sm + 100096);

    int tid = threadIdx.x;
    int b = blockIdx.x >> 7, h = blockIdx.x & 127;
    const float* xbase = x + (size_t)b * 64 * 16384 + h * 128;

    #pragma unroll
    for (int j = 0; j < 8; j++) {
        int idx4 = tid + j * 256;
        int i = idx4 >> 5, wq = idx4 & 31;
        *(float4*)(xs + i*132 + wq*4) = *(const float4*)(xbase + i*16384 + wq*4);
    }
    #pragma unroll
    for (int j = 0; j < 8; j++)
        ((ulonglong2*)bwd)[tid + j*256] = ((const ulonglong2*)g_bw2)[tid + j*256];
    {
        const float* Abx = g_Ax + (size_t)(b*128 + h) * 1024;
        const float* Aby = g_Ay + (size_t)(b*128 + h) * 1024;
        float4 vx = *(const float4*)(Abx + tid*4);
        float4 vy = *(const float4*)(Aby + tid*4);
        Ax2[tid*4+0] = pk2(vx.x,vx.x); Ax2[tid*4+1] = pk2(vx.y,vx.y);
        Ax2[tid*4+2] = pk2(vx.z,vx.z); Ax2[tid*4+3] = pk2(vx.w,vx.w);
        Ay2[tid*4+0] = pk2(vy.x,vy.x); Ay2[tid*4+1] = pk2(vy.y,vy.y);
        Ay2[tid*4+2] = pk2(vy.z,vy.z); Ay2[tid*4+3] = pk2(vy.w,vy.w);
    }
    for (int e = tid; e < 1024; e += 256) {
        int l = e >> 6, wp = e & 63;
        float s0, c0, s1, c1;
        sincospif((float)(l * (2*wp))   * (1.f/64.f), &s0, &c0);
        sincospif((float)(l * (2*wp+1)) * (1.f/64.f), &s1, &c1);
        tcw[l*66+wp] = pk2(c0, c1);
        tsw[l*66+wp] = pk2(-s0, -s1);
    }
    if (tid < 64) { pb[tid] = bypb[tid]; pj[tid] = g_proj[b*64 + tid]; }
    __syncthreads();

    int o0 = (tid >> 4) * 4, wL = tid & 15;
    int wA = wL * 4;          // w block A: 4L..4L+3
    int wB = 64 + wL * 4;     // w block B
    u64 acc[4][4];
    #pragma unroll
    for (int j = 0; j < 4; j++) { acc[j][0]=acc[j][1]=acc[j][2]=acc[j][3]=0ull; }

    #pragma unroll 4
    for (int i = 0; i < 64; i++) {
        ulonglong2 xa = *(ulonglong2*)(xs + i*132 + wA);
        ulonglong2 xc = *(ulonglong2*)(xs + i*132 + wB);
        ulonglong2 b01 = *(ulonglong2*)(bwd + i*64 + o0);
        ulonglong2 b23 = *(ulonglong2*)(bwd + i*64 + o0 + 2);
        fma2(acc[0][0], b01.x, xa.x); fma2(acc[0][1], b01.x, xa.y);
        fma2(acc[0][2], b01.x, xc.x); fma2(acc[0][3], b01.x, xc.y);
        fma2(acc[1][0], b01.y, xa.x); fma2(acc[1][1], b01.y, xa.y);
        fma2(acc[1][2], b01.y, xc.x); fma2(acc[1][3], b01.y, xc.y);
        fma2(acc[2][0], b23.x, xa.x); fma2(acc[2][1], b23.x, xa.y);
        fma2(acc[2][2], b23.x, xc.x); fma2(acc[2][3], b23.x, xc.y);
        fma2(acc[3][0], b23.y, xa.x); fma2(acc[3][1], b23.y, xa.y);
        fma2(acc[3][2], b23.y, xc.x); fma2(acc[3][3], b23.y, xc.y);
    }
    #pragma unroll 4
    for (int l = 0; l < 16; l++) {
        // w block A uses wp = 2L,2L+1 ; block B uses wp = 32+2L,32+2L+1
        ulonglong2 cA = *(ulonglong2*)(tcw + l*66 + 2*wL);
        ulonglong2 cB = *(ulonglong2*)(tcw + l*66 + 32 + 2*wL);
        ulonglong2 sA = *(ulonglong2*)(tsw + l*66 + 2*wL);
        ulonglong2 sB = *(ulonglong2*)(tsw + l*66 + 32 + 2*wL);
        #pragma unroll
        for (int j = 0; j < 4; j++) {
            u64 ax = Ax2[(o0+j)*16 + l];
            u64 ay = Ay2[(o0+j)*16 + l];
            fma2(acc[j][0], ax, cA.x); fma2(acc[j][0], ay, sA.x);
            fma2(acc[j][1], ax, cA.y); fma2(acc[j][1], ay, sA.y);
            fma2(acc[j][2], ax, cB.x); fma2(acc[j][2], ay, sB.x);
            fma2(acc[j][3], ax, cB.y); fma2(acc[j][3], ay, sB.y);
        }
    }
    float* obase = out + (size_t)b * 64 * 16384 + h * 128;
    const float is2 = 0.70710678118654752f;
    #pragma unroll
    for (int j = 0; j < 4; j++) {
        int o = o0 + j;
        float bias = pb[o], pr = pj[o];
        float g[8];
        #pragma unroll
        for (int p = 0; p < 4; p++) {
            float2 t = up2(acc[j][p]);
            float v0 = t.x + bias, v1 = t.y + bias;
            g[2*p]   = 0.5f * v0 * (1.f + erff(v0 * is2)) + pr;
            g[2*p+1] = 0.5f * v1 * (1.f + erff(v1 * is2)) + pr;
        }
        *(float4*)(obase + o*16384 + wA) = make_float4(g[0],g[1],g[2],g[3]);
        *(float4*)(obase + o*16384 + wB) = make_float4(g[4],g[5],g[6],g[7]);
    }
}

extern "C" void kernel_launch(void* const* d_in, const int* in_sizes, int n_in,
                              void* d_out, int out_size) {
    const float* x     = (const float*)d_in[0];
    const float* t_emb = (const float*)d_in[1];
    const float* wr    = (const float*)d_in[2];
    const float* wi    = (const float*)d_in[3];
    const float* bypw  = (const float*)d_in[4];
    const float* bypb  = (const float*)d_in[5];
    const float* tw    = (const float*)d_in[6];
    const float* tb    = (const float*)d_in[7];
    float* out = (float*)d_out;

    cudaFuncSetAttribute(k_fwd,   cudaFuncAttributeMaxDynamicSharedMemorySize, 100864);
    cudaFuncSetAttribute(k_final, cudaFuncAttributeMaxDynamicSharedMemorySize, 100352);

    k_proj<<<1024, 128>>>(t_emb, tw, tb);
    k_wt  <<<dim3(8, 128), dim3(32, 8)>>>(wr, wi);
    k_bwt <<<16, 256>>>(bypw);
    k_fwd <<<1024, 256, 100864>>>(x);
    k_spec<<<256, 256>>>();
    k_invA<<<1024, 256>>>();
    k_final<<<2048, 256, 100352>>>(x, bypb, out);
}

// round 7
// speedup vs baseline: 2.4798x; 1.1981x over previous
#include <cuda_runtime.h>
#include <math.h>

typedef unsigned long long u64;

__device__ __forceinline__ u64 pk2(float lo, float hi) {
    u64 r; asm("mov.b64 %0, {%1,%2};" : "=l"(r) : "f"(lo), "f"(hi)); return r;
}
__device__ __forceinline__ float2 up2(u64 v) {
    float2 r; asm("mov.b64 {%0,%1}, %2;" : "=f"(r.x), "=f"(r.y) : "l"(v)); return r;
}
__device__ __forceinline__ void fma2(u64& d, u64 a, u64 b) {
    asm("fma.rn.f32x2 %0, %1, %2, %3;" : "=l"(d) : "l"(a), "l"(b), "l"(d));
}
__device__ __forceinline__ u64 add2(u64 a, u64 b) {
    u64 r; asm("add.rn.f32x2 %0, %1, %2;" : "=l"(r) : "l"(a), "l"(b)); return r;
}
__device__ __forceinline__ u64 sub2(u64 a, u64 b) {
    float2 x = up2(a), y = up2(b); return pk2(x.x - y.x, x.y - y.y);
}
__device__ __forceinline__ float hadd(u64 v) { float2 t = up2(v); return t.x + t.y; }

__device__ float g_Xx [256*1024];
__device__ float g_Xy [256*1024];
__device__ float g_Wtx[256*4096];
__device__ float g_Wty[256*4096];
__device__ float g_OFx[1024*256];
__device__ float g_OFy[1024*256];
__device__ float g_Ax [16*128*64*16];   // [b][h][o][l], scaled, 2x folded
__device__ float g_Ay [16*128*64*16];
__device__ float g_bwT[4096];           // [i][o] transposed bypass weight
__device__ float g_proj[1024];

__global__ void k_proj(const float* __restrict__ t_emb, const float* __restrict__ temb_w,
                       const float* __restrict__ temb_b) {
    int bo = blockIdx.x, b = bo >> 6, o = bo & 63, tid = threadIdx.x;
    const float* te = t_emb + b * 512;
    const float* tw = temb_w + o * 512;
    float part = 0.f;
    for (int c = tid; c < 512; c += 128) {
        float v = te[c];
        part += (v / (1.f + expf(-v))) * tw[c];
    }
    for (int off = 16; off; off >>= 1) part += __shfl_down_sync(~0u, part, off);
    __shared__ float ws[4];
    if ((tid & 31) == 0) ws[tid >> 5] = part;
    __syncthreads();
    if (tid == 0) g_proj[bo] = ws[0] + ws[1] + ws[2] + ws[3] + temb_b[o];
}

// weights [i][o][kl] -> SoA [kl][o*64+i]
__global__ void k_wt(const float* __restrict__ wr, const float* __restrict__ wi) {
    __shared__ float tr[32][33], ti[32][33];
    int kl0 = blockIdx.x * 32, io0 = blockIdx.y * 32;
    int tx = threadIdx.x, ty = threadIdx.y;
    #pragma unroll
    for (int j = 0; j < 32; j += 8) {
        int io = io0 + ty + j;
        tr[ty + j][tx] = wr[io * 256 + kl0 + tx];
        ti[ty + j][tx] = wi[io * 256 + kl0 + tx];
    }
    __syncthreads();
    #pragma unroll
    for (int j = 0; j < 32; j += 8) {
        int kl = kl0 + ty + j, io = io0 + tx;
        int i = io >> 6, o = io & 63;
        g_Wtx[kl * 4096 + o * 64 + i] = tr[tx][ty + j];
        g_Wty[kl * 4096 + o * 64 + i] = ti[tx][ty + j];
    }
}

// bypass_w [o][i] -> [i][o] plain floats
__global__ void k_bwt(const float* __restrict__ bypw) {
    int t = blockIdx.x * 256 + threadIdx.x;
    int i = t >> 6, o = t & 63;
    g_bwT[i * 64 + o] = bypw[o * 64 + i];
}

// forward truncated DFT per (b,i), radix-2 fold along w in stage 1
__global__ void __launch_bounds__(256, 2) k_fwd(const float* __restrict__ x) {
    extern __shared__ char sm[];
    float* xs  = (float*)sm;                // 128 x 132  (after fold: [h][0..63]=xe, [h][64..127]=xo)
    u64*   tc  = (u64*)(sm + 67584);        // 16 x 65 pair table (cos)
    u64*   ts  = (u64*)(sm + 75904);        // (-sin)
    float* Ysx = (float*)(sm + 84224);      // [l][h] stride 130
    float* Ysy = (float*)(sm + 92544);
    int tid = threadIdx.x;
    const float* xb = x + (size_t)blockIdx.x * 16384;

    #pragma unroll
    for (int j = 0; j < 16; j++) {
        int idx4 = tid + j * 256;
        int row = idx4 >> 5, wq = idx4 & 31;
        *(float4*)(xs + row * 132 + wq * 4) = ((const float4*)xb)[idx4];
    }
    for (int e = tid; e < 1024; e += 256) {
        int m = e >> 6, p = e & 63;
        float s0, c0, s1, c1;
        sincospif((float)(m * (2 * p))     * (1.f / 64.f), &s0, &c0);
        sincospif((float)(m * (2 * p + 1)) * (1.f / 64.f), &s1, &c1);
        tc[m * 65 + p] = pk2(c0, c1);
        ts[m * 65 + p] = pk2(-s0, -s1);
    }
    __syncthreads();

    // in-place radix-2 fold: xe = x[w]+x[w+64] -> [w], xo = x[w]-x[w+64] -> [w+64]
    #pragma unroll
    for (int j = 0; j < 8; j++) {
        int idx = tid + j * 256;           // 2048 float4-pairs
        int h = idx >> 4, q = idx & 15;
        float4* pe = (float4*)(xs + h * 132 + q * 4);
        float4* po = (float4*)(xs + h * 132 + 64 + q * 4);
        float4 a = *pe, bq = *po;
        *pe = make_float4(a.x + bq.x, a.y + bq.y, a.z + bq.z, a.w + bq.w);
        *po = make_float4(a.x - bq.x, a.y - bq.y, a.z - bq.z, a.w - bq.w);
    }
    __syncthreads();

    { // stage 1: Y[l][h]; even l uses xe, odd l uses xo, 64 w's each
        int h_low = tid >> 3;
        int lp = tid & 7, le = 2 * lp, lo = le + 1;
        u64 aR[4][2], aI[4][2];
        #pragma unroll
        for (int r = 0; r < 4; r++) { aR[r][0]=aR[r][1]=aI[r][0]=aI[r][1]=0ull; }
        #pragma unroll 2
        for (int w = 0; w < 64; w += 4) {
            int wp = w >> 1;
            ulonglong2 e0 = *(ulonglong2*)(xs + (h_low +  0)*132 + w);
            ulonglong2 e1 = *(ulonglong2*)(xs + (h_low + 32)*132 + w);
            ulonglong2 e2 = *(ulonglong2*)(xs + (h_low + 64)*132 + w);
            ulonglong2 e3 = *(ulonglong2*)(xs + (h_low + 96)*132 + w);
            ulonglong2 o0 = *(ulonglong2*)(xs + (h_low +  0)*132 + 64 + w);
            ulonglong2 o1 = *(ulonglong2*)(xs + (h_low + 32)*132 + 64 + w);
            ulonglong2 o2 = *(ulonglong2*)(xs + (h_low + 64)*132 + 64 + w);
            ulonglong2 o3 = *(ulonglong2*)(xs + (h_low + 96)*132 + 64 + w);
            u64 ce0 = tc[le*65+wp], ce1 = tc[le*65+wp+1];
            u64 se0 = ts[le*65+wp], se1 = ts[le*65+wp+1];
            u64 co0 = tc[lo*65+wp], co1 = tc[lo*65+wp+1];
            u64 so0 = ts[lo*65+wp], so1 = ts[lo*65+wp+1];
            fma2(aR[0][0], e0.x, ce0); fma2(aR[0][0], e0.y, ce1);
            fma2(aI[0][0], e0.x, se0); fma2(aI[0][0], e0.y, se1);
            fma2(aR[1][0], e1.x, ce0); fma2(aR[1][0], e1.y, ce1);
            fma2(aI[1][0], e1.x, se0); fma2(aI[1][0], e1.y, se1);
            fma2(aR[2][0], e2.x, ce0); fma2(aR[2][0], e2.y, ce1);
            fma2(aI[2][0], e2.x, se0); fma2(aI[2][0], e2.y, se1);
            fma2(aR[3][0], e3.x, ce0); fma2(aR[3][0], e3.y, ce1);
            fma2(aI[3][0], e3.x, se0); fma2(aI[3][0], e3.y, se1);
            fma2(aR[0][1], o0.x, co0); fma2(aR[0][1], o0.y, co1);
            fma2(aI[0][1], o0.x, so0); fma2(aI[0][1], o0.y, so1);
            fma2(aR[1][1], o1.x, co0); fma2(aR[1][1], o1.y, co1);
            fma2(aI[1][1], o1.x, so0); fma2(aI[1][1], o1.y, so1);
            fma2(aR[2][1], o2.x, co0); fma2(aR[2][1], o2.y, co1);
            fma2(aI[2][1], o2.x, so0); fma2(aI[2][1], o2.y, so1);
            fma2(aR[3][1], o3.x, co0); fma2(aR[3][1], o3.y, co1);
            fma2(aI[3][1], o3.x, so0); fma2(aI[3][1], o3.y, so1);
        }
        #pragma unroll
        for (int r = 0; r < 4; r++)
            #pragma unroll
            for (int c = 0; c < 2; c++) {
                Ysx[(le+c)*130 + h_low + 32*r] = hadd(aR[r][c]);
                Ysy[(le+c)*130 + h_low + 32*r] = hadd(aI[r][c]);
            }
    }
    __syncthreads();

    { // stage 2: X[k][l] = (1/128) sum_h e^{-i k h th} Y[h][l]
        int k = tid >> 4, l = tid & 15;
        u64 aA=0ull, aB=0ull, aC=0ull, aD=0ull;
        #pragma unroll 8
        for (int hp = 0; hp < 64; hp++) {
            u64 tck = tc[k*65+hp], tsk = ts[k*65+hp];
            u64 Yxp = *(u64*)(Ysx + l*130 + 2*hp);
            u64 Yyp = *(u64*)(Ysy + l*130 + 2*hp);
            fma2(aA, tck, Yxp); fma2(aB, tsk, Yyp);
            fma2(aC, tck, Yyp); fma2(aD, tsk, Yxp);
        }
        g_Xx[tid*1024 + blockIdx.x] = (hadd(aA) - hadd(aB)) * 0.0078125f;
        g_Xy[tid*1024 + blockIdx.x] = (hadd(aC) + hadd(aD)) * 0.0078125f;
    }
}

// spectral mix per mode kl
__global__ void __launch_bounds__(256) k_spec() {
    __shared__ float Xxs[1024], Xys[1024];
    __shared__ float Wxs[64*66], Wys[64*66];
    int kl = blockIdx.x, tid = threadIdx.x;
    for (int j = tid; j < 1024; j += 256) { Xxs[j] = g_Xx[kl*1024+j]; Xys[j] = g_Xy[kl*1024+j]; }
    for (int j = tid; j < 4096; j += 256) {
        int o = j >> 6, i = j & 63;
        Wxs[o*66+i] = g_Wtx[kl*4096+j];
        Wys[o*66+i] = g_Wty[kl*4096+j];
    }
    __syncthreads();
    int b = tid >> 4, o0 = tid & 15;
    u64 aA[4], aB[4], aC[4], aD[4];
    #pragma unroll
    for (int j = 0; j < 4; j++) { aA[j]=aB[j]=aC[j]=aD[j]=0ull; }
    #pragma unroll 4
    for (int ip = 0; ip < 32; ip++) {
        u64 Xxp = *(u64*)(Xxs + b*64 + 2*ip);
        u64 Xyp = *(u64*)(Xys + b*64 + 2*ip);
        #pragma unroll
        for (int j = 0; j < 4; j++) {
            int o = o0 + 16*j;
            u64 Wxp = *(u64*)(Wxs + o*66 + 2*ip);
            u64 Wyp = *(u64*)(Wys + o*66 + 2*ip);
            fma2(aA[j], Xxp, Wxp); fma2(aB[j], Xyp, Wyp);
            fma2(aC[j], Xxp, Wyp); fma2(aD[j], Xyp, Wxp);
        }
    }
    #pragma unroll
    for (int j = 0; j < 4; j++) {
        int bo = b*64 + o0 + 16*j;
        g_OFx[bo*256 + kl] = hadd(aA[j]) - hadd(aB[j]);
        g_OFy[bo*256 + kl] = hadd(aC[j]) + hadd(aD[j]);
    }
}

// inverse along h per (b,o): A[h][l] = sc * sum_k F[k,l] e^{+i k h th}
__global__ void __launch_bounds__(256) k_invA() {
    __shared__ u64 tcT[128*9], tsT[128*9];
    __shared__ float Fxs[16*18], Fys[16*18];
    int tid = threadIdx.x, bo = blockIdx.x;
    for (int e = tid; e < 1024; e += 256) {
        int h = e >> 3, kp = e & 7;
        float s0, c0, s1, c1;
        sincospif((float)(h * (2*kp))   * (1.f/64.f), &s0, &c0);
        sincospif((float)(h * (2*kp+1)) * (1.f/64.f), &s1, &c1);
        tcT[h*9+kp] = pk2(c0, c1);
        tsT[h*9+kp] = pk2(-s0, -s1);
    }
    {
        int k = tid >> 4, l = tid & 15;
        Fxs[l*18+k] = g_OFx[bo*256 + tid];
        Fys[l*18+k] = g_OFy[bo*256 + tid];
    }
    __syncthreads();
    int h = tid >> 1, l0 = (tid & 1) * 8;
    u64 aA[8], aB[8], aC[8], aD[8];
    #pragma unroll
    for (int j = 0; j < 8; j++) { aA[j]=aB[j]=aC[j]=aD[j]=0ull; }
    #pragma unroll
    for (int kp = 0; kp < 8; kp++) {
        u64 tck = tcT[h*9+kp], tsk = tsT[h*9+kp];
        #pragma unroll
        for (int j = 0; j < 8; j++) {
            u64 Fxp = *(u64*)(Fxs + (l0+j)*18 + 2*kp);
            u64 Fyp = *(u64*)(Fys + (l0+j)*18 + 2*kp);
            fma2(aA[j], tck, Fxp); fma2(aB[j], tsk, Fyp);
            fma2(aC[j], tck, Fyp); fma2(aD[j], tsk, Fxp);
        }
    }
    int b = bo >> 6, o = bo & 63;
    float* ox = g_Ax + ((size_t)(b*128 + h)*64 + o)*16 + l0;
    float* oy = g_Ay + ((size_t)(b*128 + h)*64 + o)*16 + l0;
    float rx[8], ry[8];
    #pragma unroll
    for (int j = 0; j < 8; j++) {
        float sc = (l0 + j == 0) ? 0.0078125f : 0.015625f;
        rx[j] = (hadd(aA[j]) + hadd(aB[j])) * sc;
        ry[j] = (hadd(aC[j]) - hadd(aD[j])) * sc;
    }
    *(float4*)(ox)   = make_float4(rx[0],rx[1],rx[2],rx[3]);
    *(float4*)(ox+4) = make_float4(rx[4],rx[5],rx[6],rx[7]);
    *(float4*)(oy)   = make_float4(ry[0],ry[1],ry[2],ry[3]);
    *(float4*)(oy+4) = make_float4(ry[4],ry[5],ry[6],ry[7]);
}

// final fused per (b,h): irfft E/O fold + bypass GEMM + GeLU + temb, 3 CTAs/SM
__global__ void __launch_bounds__(256, 3) k_final(const float* __restrict__ x,
                                                  const float* __restrict__ bypb,
                                                  float* __restrict__ out) {
    extern __shared__ char sm[];
    float* xs  = (float*)sm;            // 64 x 132            33792 B
    float* bw  = (float*)(sm + 33792);  // [i][o] floats       16384 B
    float* Axs = (float*)(sm + 50176);  // [o*16+l]             4096 B
    float* Ays = (float*)(sm + 54272);  //                      4096 B
    u64*   tcw = (u64*)(sm + 58368);    // [l][wp<32] stride34  4352 B
    u64*   tsw = (u64*)(sm + 62720);    //                      4352 B
    float* pb  = (float*)(sm + 67072);  // 64 f
    float* pj  = (float*)(sm + 67328);  // 64 f  -> total 67584

    int tid = threadIdx.x;
    int b = blockIdx.x >> 7, h = blockIdx.x & 127;
    const float* xbase = x + (size_t)b * 64 * 16384 + h * 128;

    #pragma unroll
    for (int j = 0; j < 8; j++) {
        int idx4 = tid + j * 256;
        int i = idx4 >> 5, wq = idx4 & 31;
        *(float4*)(xs + i*132 + wq*4) = *(const float4*)(xbase + i*16384 + wq*4);
    }
    #pragma unroll
    for (int j = 0; j < 4; j++)
        ((float4*)bw)[tid + j*256] = ((const float4*)g_bwT)[tid + j*256];
    {
        const float* Abx = g_Ax + (size_t)(b*128 + h) * 1024;
        const float* Aby = g_Ay + (size_t)(b*128 + h) * 1024;
        *(float4*)(Axs + tid*4) = *(const float4*)(Abx + tid*4);
        *(float4*)(Ays + tid*4) = *(const float4*)(Aby + tid*4);
    }
    for (int e = tid; e < 512; e += 256) {
        int l = e >> 5, wp = e & 31;
        float s0, c0, s1, c1;
        sincospif((float)(l * (2*wp))   * (1.f/64.f), &s0, &c0);
        sincospif((float)(l * (2*wp+1)) * (1.f/64.f), &s1, &c1);
        tcw[l*34+wp] = pk2(c0, c1);
        tsw[l*34+wp] = pk2(-s0, -s1);
    }
    if (tid < 64) { pb[tid] = bypb[tid]; pj[tid] = g_proj[b*64 + tid]; }
    __syncthreads();

    int o0 = (tid >> 4) * 4, wL = tid & 15;
    int wA = wL * 4;          // w block A: 4L..4L+3
    int wB = 64 + wL * 4;     // w block B = A + 64

    // --- irfft fold first (E/O registers die before GEMM) ---
    u64 acc[4][4];
    {
        u64 E[4][2], O[4][2];
        #pragma unroll
        for (int j = 0; j < 4; j++) { E[j][0]=E[j][1]=O[j][0]=O[j][1]=0ull; }
        #pragma unroll 4
        for (int l = 0; l < 16; l++) {
            ulonglong2 cA = *(ulonglong2*)(tcw + l*34 + 2*wL);
            ulonglong2 sA = *(ulonglong2*)(tsw + l*34 + 2*wL);
            #pragma unroll
            for (int j = 0; j < 4; j++) {
                u64 ax = pk2(Axs[(o0+j)*16 + l], Axs[(o0+j)*16 + l]);
                u64 ay = pk2(Ays[(o0+j)*16 + l], Ays[(o0+j)*16 + l]);
                if ((l & 1) == 0) {
                    fma2(E[j][0], ax, cA.x); fma2(E[j][0], ay, sA.x);
                    fma2(E[j][1], ax, cA.y); fma2(E[j][1], ay, sA.y);
                } else {
                    fma2(O[j][0], ax, cA.x); fma2(O[j][0], ay, sA.x);
                    fma2(O[j][1], ax, cA.y); fma2(O[j][1], ay, sA.y);
                }
            }
        }
        #pragma unroll
        for (int j = 0; j < 4; j++) {
            acc[j][0] = add2(E[j][0], O[j][0]);   // block A = E + O
            acc[j][1] = add2(E[j][1], O[j][1]);
            acc[j][2] = sub2(E[j][0], O[j][0]);   // block B = E - O
            acc[j][3] = sub2(E[j][1], O[j][1]);
        }
    }

    // --- bypass GEMM accumulates on top ---
    #pragma unroll 4
    for (int i = 0; i < 64; i++) {
        ulonglong2 xa = *(ulonglong2*)(xs + i*132 + wA);
        ulonglong2 xc = *(ulonglong2*)(xs + i*132 + wB);
        float2 b01f = *(float2*)(bw + i*64 + o0);
        float2 b23f = *(float2*)(bw + i*64 + o0 + 2);
        u64 b0 = pk2(b01f.x, b01f.x), b1 = pk2(b01f.y, b01f.y);
        u64 b2 = pk2(b23f.x, b23f.x), b3 = pk2(b23f.y, b23f.y);
        fma2(acc[0][0], b0, xa.x); fma2(acc[0][1], b0, xa.y);
        fma2(acc[0][2], b0, xc.x); fma2(acc[0][3], b0, xc.y);
        fma2(acc[1][0], b1, xa.x); fma2(acc[1][1], b1, xa.y);
        fma2(acc[1][2], b1, xc.x); fma2(acc[1][3], b1, xc.y);
        fma2(acc[2][0], b2, xa.x); fma2(acc[2][1], b2, xa.y);
        fma2(acc[2][2], b2, xc.x); fma2(acc[2][3], b2, xc.y);
        fma2(acc[3][0], b3, xa.x); fma2(acc[3][1], b3, xa.y);
        fma2(acc[3][2], b3, xc.x); fma2(acc[3][3], b3, xc.y);
    }

    float* obase = out + (size_t)b * 64 * 16384 + h * 128;
    const float is2 = 0.70710678118654752f;
    #pragma unroll
    for (int j = 0; j < 4; j++) {
        int o = o0 + j;
        float bias = pb[o], pr = pj[o];
        float g[8];
        #pragma unroll
        for (int p = 0; p < 4; p++) {
            float2 t = up2(acc[j][p]);
            float v0 = t.x + bias, v1 = t.y + bias;
            g[2*p]   = 0.5f * v0 * (1.f + erff(v0 * is2)) + pr;
            g[2*p+1] = 0.5f * v1 * (1.f + erff(v1 * is2)) + pr;
        }
        *(float4*)(obase + o*16384 + wA) = make_float4(g[0],g[1],g[2],g[3]);
        *(float4*)(obase + o*16384 + wB) = make_float4(g[4],g[5],g[6],g[7]);
    }
}

extern "C" void kernel_launch(void* const* d_in, const int* in_sizes, int n_in,
                              void* d_out, int out_size) {
    const float* x     = (const float*)d_in[0];
    const float* t_emb = (const float*)d_in[1];
    const float* wr    = (const float*)d_in[2];
    const float* wi    = (const float*)d_in[3];
    const float* bypw  = (const float*)d_in[4];
    const float* bypb  = (const float*)d_in[5];
    const float* tw    = (const float*)d_in[6];
    const float* tb    = (const float*)d_in[7];
    float* out = (float*)d_out;

    cudaFuncSetAttribute(k_fwd,   cudaFuncAttributeMaxDynamicSharedMemorySize, 100864);
    cudaFuncSetAttribute(k_final, cudaFuncAttributeMaxDynamicSharedMemorySize, 67584);

    k_proj<<<1024, 128>>>(t_emb, tw, tb);
    k_wt  <<<dim3(8, 128), dim3(32, 8)>>>(wr, wi);
    k_bwt <<<16, 256>>>(bypw);
    k_fwd <<<1024, 256, 100864>>>(x);
    k_spec<<<256, 256>>>();
    k_invA<<<1024, 256>>>();
    k_final<<<2048, 256, 67584>>>(x, bypb, out);
}